// round 1
// baseline (speedup 1.0000x reference)
#include <cuda_runtime.h>
#include <math.h>

// Problem dims
#define BB 16
#define NN 512
#define DD 512
#define RR 8
#define TD (3*DD)

// Scratch (allocation-free: __device__ globals)
static __device__ float g_h[(size_t)BB*NN*DD];          //  16 MB
static __device__ float g_hW[(size_t)RR*BB*NN*DD];      // 128 MB
static __device__ float g_agg[(size_t)BB*NN*DD];        //  16 MB
static __device__ float g_gi[(size_t)BB*NN*TD];         //  48 MB
static __device__ float g_gh[(size_t)BB*NN*TD];         //  48 MB

// Tiling
#define BM 128
#define BN 128
#define BK 16
#define TM 8
#define TN 8
// 256 threads = (BM/TM)*(BN/TN)

#define MM_COMPUTE()                                                        \
  do {                                                                      \
    _Pragma("unroll")                                                       \
    for (int k = 0; k < BK; ++k) {                                          \
      float a_[TM], b_[TN];                                                 \
      _Pragma("unroll") for (int i_ = 0; i_ < TM; i_++) a_[i_] = As[k][ty*TM + i_]; \
      _Pragma("unroll") for (int j_ = 0; j_ < TN; j_++) b_[j_] = Bs[k][tx*TN + j_]; \
      _Pragma("unroll") for (int i_ = 0; i_ < TM; i_++)                     \
        _Pragma("unroll") for (int j_ = 0; j_ < TN; j_++)                   \
          acc[i_][j_] += a_[i_] * b_[j_];                                   \
    }                                                                       \
  } while (0)

// ---------------------------------------------------------------------------
// K1: hW[r, b*N+i, e] = sum_d h[b*N+i, d] * msg_W[r, e, d]    (NT GEMM)
// grid: (8192/BM, 512/BN, R)
// ---------------------------------------------------------------------------
__global__ void __launch_bounds__(256, 2)
k_hw(const float* __restrict__ nodes, const float* __restrict__ msg_W, int step) {
  const float* A = (step == 0) ? nodes : g_h;          // [8192, 512] row-major
  const int r    = blockIdx.z;
  const int row0 = blockIdx.x * BM;
  const int col0 = blockIdx.y * BN;
  const float* Bm = msg_W + (size_t)r * DD * DD;       // access [e][d]
  float* C = g_hW + (size_t)r * BB * NN * DD;

  __shared__ float As[BK][BM + 4];
  __shared__ float Bs[BK][BN + 4];
  const int tid = threadIdx.x;
  const int tx = tid & 15, ty = tid >> 4;
  float acc[TM][TN] = {};

  for (int k0 = 0; k0 < DD; k0 += BK) {
#pragma unroll
    for (int l = 0; l < 2; ++l) {
      int idx = tid + l * 256;
      int m = idx >> 2, ks = (idx & 3) << 2;
      float4 va = *(const float4*)(A  + (size_t)(row0 + m) * DD + k0 + ks);
      As[ks+0][m] = va.x; As[ks+1][m] = va.y; As[ks+2][m] = va.z; As[ks+3][m] = va.w;
      float4 vb = *(const float4*)(Bm + (size_t)(col0 + m) * DD + k0 + ks);
      Bs[ks+0][m] = vb.x; Bs[ks+1][m] = vb.y; Bs[ks+2][m] = vb.z; Bs[ks+3][m] = vb.w;
    }
    __syncthreads();
    MM_COMPUTE();
    __syncthreads();
  }
#pragma unroll
  for (int i = 0; i < TM; i++) {
    float* cp = C + (size_t)(row0 + ty*TM + i) * DD + col0 + tx*TN;
#pragma unroll
    for (int j = 0; j < TN; j += 4) {
      float4 v = make_float4(acc[i][j], acc[i][j+1], acc[i][j+2], acc[i][j+3]);
      *(float4*)(cp + j) = v;
    }
  }
}

// ---------------------------------------------------------------------------
// K2: agg[b,i,e] = sum_r sum_j edges[b,r,i,j] * hW[r,b,j,e] + sum_r msg_b[r,e]
// grid: (512/BM, 512/BN, B);  K-loop = r outer (8) x j tiles (512/BK)
// ---------------------------------------------------------------------------
__global__ void __launch_bounds__(256, 2)
k_agg(const float* __restrict__ edges, const float* __restrict__ msg_b) {
  const int b    = blockIdx.z;
  const int row0 = blockIdx.x * BM;
  const int col0 = blockIdx.y * BN;
  __shared__ float As[BK][BM + 4];
  __shared__ float Bs[BK][BN + 4];
  const int tid = threadIdx.x;
  const int tx = tid & 15, ty = tid >> 4;
  float acc[TM][TN] = {};

  for (int r = 0; r < RR; ++r) {
    const float* A  = edges + ((size_t)(b * RR + r)) * NN * NN;  // [i][j]
    const float* Bp = g_hW  + ((size_t)(r * BB + b)) * NN * DD;  // [j][e]
    for (int k0 = 0; k0 < NN; k0 += BK) {
#pragma unroll
      for (int l = 0; l < 2; ++l) {              // A tile: k(j)-contiguous
        int idx = tid + l * 256;
        int m = idx >> 2, ks = (idx & 3) << 2;
        float4 va = *(const float4*)(A + (size_t)(row0 + m) * NN + k0 + ks);
        As[ks+0][m] = va.x; As[ks+1][m] = va.y; As[ks+2][m] = va.z; As[ks+3][m] = va.w;
      }
#pragma unroll
      for (int l = 0; l < 2; ++l) {              // B tile: n(e)-contiguous (NN)
        int idx = tid + l * 256;
        int k = idx >> 5, ns = (idx & 31) << 2;
        float4 vb = *(const float4*)(Bp + (size_t)(k0 + k) * DD + col0 + ns);
        *(float4*)(&Bs[k][ns]) = vb;
      }
      __syncthreads();
      MM_COMPUTE();
      __syncthreads();
    }
  }
  // epilogue: += sum_r msg_b[r, e]
  float bsum[TN];
#pragma unroll
  for (int j = 0; j < TN; j++) {
    float s = 0.f;
#pragma unroll
    for (int r = 0; r < RR; r++) s += msg_b[r * DD + col0 + tx*TN + j];
    bsum[j] = s;
  }
#pragma unroll
  for (int i = 0; i < TM; i++) {
    float* cp = g_agg + (size_t)b * NN * DD + (size_t)(row0 + ty*TM + i) * DD + col0 + tx*TN;
#pragma unroll
    for (int j = 0; j < TN; j += 4) {
      float4 v = make_float4(acc[i][j] + bsum[j], acc[i][j+1] + bsum[j+1],
                             acc[i][j+2] + bsum[j+2], acc[i][j+3] + bsum[j+3]);
      *(float4*)(cp + j) = v;
    }
  }
}

// ---------------------------------------------------------------------------
// K3: gates  C[8192, 1536] = A[8192,512] @ W^T + bias      (NT GEMM)
// a_sel: 0 -> g_agg, 1 -> nodes arg, 2 -> g_h.  out_sel: 0 -> g_gi, 1 -> g_gh
// grid: (8192/BM, 1536/BN)
// ---------------------------------------------------------------------------
__global__ void __launch_bounds__(256, 2)
k_gates(const float* __restrict__ nodes, const float* __restrict__ W,
        const float* __restrict__ bias, int a_sel, int out_sel) {
  const float* A = (a_sel == 0) ? g_agg : ((a_sel == 1) ? nodes : g_h);
  float* C = out_sel ? g_gh : g_gi;
  const int row0 = blockIdx.x * BM;
  const int col0 = blockIdx.y * BN;
  __shared__ float As[BK][BM + 4];
  __shared__ float Bs[BK][BN + 4];
  const int tid = threadIdx.x;
  const int tx = tid & 15, ty = tid >> 4;
  float acc[TM][TN] = {};

  for (int k0 = 0; k0 < DD; k0 += BK) {
#pragma unroll
    for (int l = 0; l < 2; ++l) {
      int idx = tid + l * 256;
      int m = idx >> 2, ks = (idx & 3) << 2;
      float4 va = *(const float4*)(A + (size_t)(row0 + m) * DD + k0 + ks);
      As[ks+0][m] = va.x; As[ks+1][m] = va.y; As[ks+2][m] = va.z; As[ks+3][m] = va.w;
      float4 vb = *(const float4*)(W + (size_t)(col0 + m) * DD + k0 + ks);
      Bs[ks+0][m] = vb.x; Bs[ks+1][m] = vb.y; Bs[ks+2][m] = vb.z; Bs[ks+3][m] = vb.w;
    }
    __syncthreads();
    MM_COMPUTE();
    __syncthreads();
  }
  float bv[TN];
#pragma unroll
  for (int j = 0; j < TN; j++) bv[j] = bias[col0 + tx*TN + j];
#pragma unroll
  for (int i = 0; i < TM; i++) {
    float* cp = C + (size_t)(row0 + ty*TM + i) * TD + col0 + tx*TN;
#pragma unroll
    for (int j = 0; j < TN; j += 4) {
      float4 v = make_float4(acc[i][j] + bv[j], acc[i][j+1] + bv[j+1],
                             acc[i][j+2] + bv[j+2], acc[i][j+3] + bv[j+3]);
      *(float4*)(cp + j) = v;
    }
  }
}

// ---------------------------------------------------------------------------
// K4: GRU elementwise update; writes g_h
// ---------------------------------------------------------------------------
__global__ void k_gru(const float* __restrict__ nodes, int step) {
  int idx = blockIdx.x * blockDim.x + threadIdx.x;   // < B*N*D = 4M
  const float* hsrc = (step == 0) ? nodes : g_h;
  int d   = idx & (DD - 1);
  int row = idx >> 9;
  const float* gi = g_gi + (size_t)row * TD;
  const float* gh = g_gh + (size_t)row * TD;
  float ir = gi[d],       hr = gh[d];
  float iz = gi[DD + d],  hz = gh[DD + d];
  float in_ = gi[2*DD + d], hn = gh[2*DD + d];
  float r = 1.f / (1.f + expf(-(ir + hr)));
  float z = 1.f / (1.f + expf(-(iz + hz)));
  float n = tanhf(in_ + r * hn);
  float h = hsrc[idx];
  g_h[idx] = (1.f - z) * n + z * h;
}

// ---------------------------------------------------------------------------
// K5: out[b,d] = mean_i h[b,i,d]
// ---------------------------------------------------------------------------
__global__ void k_mean(float* __restrict__ out) {
  int b = blockIdx.x;
  int d = threadIdx.x;                 // 512 threads
  const float* hp = g_h + (size_t)b * NN * DD + d;
  float s = 0.f;
  for (int i = 0; i < NN; ++i) s += hp[(size_t)i * DD];
  out[b * DD + d] = s * (1.0f / NN);
}

// ---------------------------------------------------------------------------
extern "C" void kernel_launch(void* const* d_in, const int* in_sizes, int n_in,
                              void* d_out, int out_size) {
  const float* nodes = (const float*)d_in[0];
  const float* edges = (const float*)d_in[1];
  const float* msg_W = (const float*)d_in[2];
  const float* msg_b = (const float*)d_in[3];
  const float* w_ih  = (const float*)d_in[4];
  const float* w_hh  = (const float*)d_in[5];
  const float* b_ih  = (const float*)d_in[6];
  const float* b_hh  = (const float*)d_in[7];
  float* out = (float*)d_out;

  dim3 blk(256);
  for (int s = 0; s < 2; ++s) {
    k_hw   <<<dim3(BB*NN/BM, DD/BN, RR), blk>>>(nodes, msg_W, s);
    k_agg  <<<dim3(NN/BM, DD/BN, BB),    blk>>>(edges, msg_b);
    k_gates<<<dim3(BB*NN/BM, TD/BN),     blk>>>(nodes, w_ih, b_ih, 0, 0);
    k_gates<<<dim3(BB*NN/BM, TD/BN),     blk>>>(nodes, w_hh, b_hh, (s == 0) ? 1 : 2, 1);
    k_gru  <<<(BB*NN*DD) / 256, 256>>>(nodes, s);
  }
  k_mean<<<BB, DD>>>(out);
}

// round 6
// speedup vs baseline: 2.3738x; 2.3738x over previous
#include <cuda_runtime.h>
#include <cuda_bf16.h>
#include <math.h>
#include <stdint.h>

// Problem dims
#define BB 16
#define NN 512
#define DD 512
#define RR 8
#define TD (3*DD)

// ---------------------------------------------------------------------------
// Scratch (__device__ globals; allocation-free)
// ---------------------------------------------------------------------------
static __device__ __align__(256) float g_h[(size_t)BB*NN*DD];
static __device__ __align__(256) float g_gi[(size_t)BB*NN*TD];
static __device__ __align__(256) float g_gh[(size_t)BB*NN*TD];
static __device__ __align__(256) float g_bias_sum[DD];

static __device__ __align__(256) __nv_bfloat16 g_hhi[(size_t)BB*NN*DD];
static __device__ __align__(256) __nv_bfloat16 g_hlo[(size_t)BB*NN*DD];
static __device__ __align__(256) __nv_bfloat16 g_ehi[(size_t)BB*RR*NN*NN];
static __device__ __align__(256) __nv_bfloat16 g_elo[(size_t)BB*RR*NN*NN];
static __device__ __align__(256) __nv_bfloat16 g_Whi[(size_t)RR*DD*DD];
static __device__ __align__(256) __nv_bfloat16 g_Wlo[(size_t)RR*DD*DD];
static __device__ __align__(256) __nv_bfloat16 g_wihhi[(size_t)TD*DD];
static __device__ __align__(256) __nv_bfloat16 g_wihlo[(size_t)TD*DD];
static __device__ __align__(256) __nv_bfloat16 g_whhhi[(size_t)TD*DD];
static __device__ __align__(256) __nv_bfloat16 g_whhlo[(size_t)TD*DD];
static __device__ __align__(256) __nv_bfloat16 g_hWThi[(size_t)RR*DD*BB*NN]; // [r][e][j]
static __device__ __align__(256) __nv_bfloat16 g_hWTlo[(size_t)RR*DD*BB*NN];
static __device__ __align__(256) __nv_bfloat16 g_agghi[(size_t)BB*NN*DD];
static __device__ __align__(256) __nv_bfloat16 g_agglo[(size_t)BB*NN*DD];

// ---------------------------------------------------------------------------
// PTX helpers (all non-'a' ISA: cp.async / ldmatrix / mma.sync)
// ---------------------------------------------------------------------------
__device__ __forceinline__ uint32_t s2u(const void* p) {
  uint32_t a;
  asm("{ .reg .u64 t; cvta.to.shared.u64 t, %1; cvt.u32.u64 %0, t; }" : "=r"(a) : "l"(p));
  return a;
}
__device__ __forceinline__ void cp16(uint32_t s, const void* g) {
  asm volatile("cp.async.cg.shared.global [%0], [%1], 16;" :: "r"(s), "l"(g));
}
#define CP_COMMIT() asm volatile("cp.async.commit_group;" ::: "memory")

#define LDSM4(r, a) \
  asm volatile("ldmatrix.sync.aligned.m8n8.x4.shared.b16 {%0,%1,%2,%3},[%4];" \
    : "=r"((r)[0]),"=r"((r)[1]),"=r"((r)[2]),"=r"((r)[3]) : "r"(a))

#define MMA(d, a, b0, b1) \
  asm volatile("mma.sync.aligned.m16n8k16.row.col.f32.bf16.bf16.f32 " \
    "{%0,%1,%2,%3},{%4,%5,%6,%7},{%8,%9},{%0,%1,%2,%3};" \
    : "+f"((d)[0]),"+f"((d)[1]),"+f"((d)[2]),"+f"((d)[3]) \
    : "r"((a)[0]),"r"((a)[1]),"r"((a)[2]),"r"((a)[3]),"r"(b0),"r"(b1))

// ---------------------------------------------------------------------------
// GEMM core: CTA 128x128x32, 8 warps (4M x 2N), warp tile 32x64
// smem rows padded to 40 bf16 (80B) -> conflict-free ldmatrix phases
// Layout/stage: Ahi @0 (10240B) | Alo @10240 | Bhi @20480 | Blo @30720
// ---------------------------------------------------------------------------
#define STAGE_BYTES 40960
#define DYN_SMEM (2*STAGE_BYTES)
#define LDP 80   // padded row pitch in bytes (40 bf16)

struct TilePtrs { const __nv_bfloat16 *ah, *al, *bh, *bl; };

template <class F>
__device__ __forceinline__ void gemm_mma(F f, int niters, int lda, int ldb,
                                         float acc[2][8][4]) {
  extern __shared__ char smem[];
  const uint32_t sb = s2u(smem);
  const int tid = threadIdx.x;
  const int lane = tid & 31, w = tid >> 5;
  const int wm = w & 3, wn = w >> 2;

  #pragma unroll
  for (int a = 0; a < 2; ++a)
    #pragma unroll
    for (int b = 0; b < 8; ++b)
      #pragma unroll
      for (int c = 0; c < 4; ++c) acc[a][b][c] = 0.f;

  auto load_stage = [&](int s, int it) {
    TilePtrs p = f(it);
    uint32_t st = sb + s * STAGE_BYTES;
    #pragma unroll
    for (int l = 0; l < 2; ++l) {
      int i = tid + l * 256;
      int r = i >> 2, c = i & 3;                 // r: 0..127 row, c: 16B chunk
      uint32_t o = (uint32_t)r * LDP + c * 16;
      const __nv_bfloat16* ga = p.ah + (size_t)r * lda + c * 8;
      const __nv_bfloat16* gl = p.al + (size_t)r * lda + c * 8;
      const __nv_bfloat16* gb = p.bh + (size_t)r * ldb + c * 8;
      const __nv_bfloat16* gc = p.bl + (size_t)r * ldb + c * 8;
      cp16(st + o,         ga);
      cp16(st + 10240 + o, gl);
      cp16(st + 20480 + o, gb);
      cp16(st + 30720 + o, gc);
    }
    CP_COMMIT();
  };

  // ldmatrix lane address offsets
  const uint32_t aLane = (uint32_t)(lane & 15) * LDP + (lane >> 4) * 16;
  const uint32_t bLane = (uint32_t)((lane & 7) + ((lane >> 4) << 3)) * LDP
                       + ((lane >> 3) & 1) * 16;

  load_stage(0, 0);
  for (int it = 0; it < niters; ++it) {
    if (it + 1 < niters) {
      load_stage((it + 1) & 1, it + 1);
      asm volatile("cp.async.wait_group 1;" ::: "memory");
    } else {
      asm volatile("cp.async.wait_group 0;" ::: "memory");
    }
    __syncthreads();
    uint32_t st = sb + (it & 1) * STAGE_BYTES;
    uint32_t aBase = st + (uint32_t)(wm * 32) * LDP + aLane;
    uint32_t bBase = st + 20480 + (uint32_t)(wn * 64) * LDP + bLane;
    #pragma unroll
    for (int k16 = 0; k16 < 2; ++k16) {
      uint32_t ah[2][4], al[2][4], bh[4][4], bl[4][4];
      #pragma unroll
      for (int mt = 0; mt < 2; ++mt) {
        uint32_t a = aBase + (uint32_t)(mt * 16) * LDP + k16 * 32;
        LDSM4(ah[mt], a);
        LDSM4(al[mt], a + 10240);
      }
      #pragma unroll
      for (int g = 0; g < 4; ++g) {
        uint32_t b = bBase + (uint32_t)(g * 16) * LDP + k16 * 32;
        LDSM4(bh[g], b);
        LDSM4(bl[g], b + 10240);
      }
      #pragma unroll
      for (int mt = 0; mt < 2; ++mt)
        #pragma unroll
        for (int g = 0; g < 4; ++g)
          #pragma unroll
          for (int t = 0; t < 2; ++t) {
            float* d = acc[mt][g * 2 + t];
            MMA(d, ah[mt], bh[g][2*t], bh[g][2*t+1]);   // hi*hi
            MMA(d, ah[mt], bl[g][2*t], bl[g][2*t+1]);   // hi*lo
            MMA(d, al[mt], bh[g][2*t], bh[g][2*t+1]);   // lo*hi
          }
    }
    __syncthreads();
  }
}

// Epilogue index helpers: element (row,col) of acc[mt][nt][cr]
//   row = row0 + wm*32 + mt*16 + (lane>>2) + ((cr>>1)<<3)
//   col = col0 + wn*64 + nt*8 + (lane&3)*2 + (cr&1)

// ---------------------------------------------------------------------------
// K1: hWT[r][e][j] = sum_d h[j,d] * W[r][e,d]; writes transposed + split
// grid (64, 4, 8)
// ---------------------------------------------------------------------------
__global__ void __launch_bounds__(256) k_hw_t() {
  const int row0 = blockIdx.x * 128, col0 = blockIdx.y * 128, r = blockIdx.z;
  auto f = [&](int it) -> TilePtrs {
    int k0 = it * 32;
    TilePtrs p;
    p.ah = g_hhi + (size_t)row0 * DD + k0;
    p.al = g_hlo + (size_t)row0 * DD + k0;
    p.bh = g_Whi + ((size_t)r * DD + col0) * DD + k0;
    p.bl = g_Wlo + ((size_t)r * DD + col0) * DD + k0;
    return p;
  };
  float acc[2][8][4];
  gemm_mma(f, 16, DD, DD, acc);
  const int lane = threadIdx.x & 31, w = threadIdx.x >> 5;
  const int wm = w & 3, wn = w >> 2, grp = lane >> 2, tig = lane & 3;
  #pragma unroll
  for (int mt = 0; mt < 2; ++mt)
    #pragma unroll
    for (int nt = 0; nt < 8; ++nt)
      #pragma unroll
      for (int cr = 0; cr < 4; ++cr) {
        int j = row0 + wm * 32 + mt * 16 + grp + ((cr >> 1) << 3);
        int e = col0 + wn * 64 + nt * 8 + tig * 2 + (cr & 1);
        float v = acc[mt][nt][cr];
        size_t o = ((size_t)r * DD + e) * (size_t)(BB * NN) + j;
        __nv_bfloat16 hh = __float2bfloat16(v);
        g_hWThi[o] = hh;
        g_hWTlo[o] = __float2bfloat16(v - __bfloat162float(hh));
      }
}

// ---------------------------------------------------------------------------
// K2: agg[b][i][e] = sum_r sum_j edges[b,r,i,j]*hWT[r][e][b*512+j] + bias_sum
// grid (4, 4, 16); niters = 8 r * 16 k-chunks = 128
// ---------------------------------------------------------------------------
__global__ void __launch_bounds__(256) k_agg_t() {
  const int b = blockIdx.z, row0 = blockIdx.x * 128, col0 = blockIdx.y * 128;
  auto f = [&](int it) -> TilePtrs {
    int r = it >> 4, k0 = (it & 15) * 32;
    TilePtrs p;
    size_t ea = ((size_t)(b * RR + r) * NN + row0) * NN + k0;
    size_t wb = ((size_t)r * DD + col0) * (size_t)(BB * NN) + (size_t)b * NN + k0;
    p.ah = g_ehi + ea;   p.al = g_elo + ea;
    p.bh = g_hWThi + wb; p.bl = g_hWTlo + wb;
    return p;
  };
  float acc[2][8][4];
  gemm_mma(f, 128, NN, BB * NN, acc);
  const int lane = threadIdx.x & 31, w = threadIdx.x >> 5;
  const int wm = w & 3, wn = w >> 2, grp = lane >> 2, tig = lane & 3;
  #pragma unroll
  for (int mt = 0; mt < 2; ++mt)
    #pragma unroll
    for (int nt = 0; nt < 8; ++nt)
      #pragma unroll
      for (int cr = 0; cr < 4; ++cr) {
        int i = row0 + wm * 32 + mt * 16 + grp + ((cr >> 1) << 3);
        int e = col0 + wn * 64 + nt * 8 + tig * 2 + (cr & 1);
        float v = acc[mt][nt][cr] + g_bias_sum[e];
        size_t o = (size_t)(b * NN + i) * DD + e;
        __nv_bfloat16 hh = __float2bfloat16(v);
        g_agghi[o] = hh;
        g_agglo[o] = __float2bfloat16(v - __bfloat162float(hh));
      }
}

// ---------------------------------------------------------------------------
// K3: gates C[8192,1536] = A @ W^T + bias (fp32 out)
// a_sel: 0 -> agg splits, 1 -> h splits; out_sel: 0 -> g_gi, 1 -> g_gh
// grid (64, 12)
// ---------------------------------------------------------------------------
__global__ void __launch_bounds__(256) k_gates_t(int a_sel, int w_sel,
                                                 const float* __restrict__ bias,
                                                 int out_sel) {
  const int row0 = blockIdx.x * 128, col0 = blockIdx.y * 128;
  const __nv_bfloat16* Ah = a_sel ? g_hhi : g_agghi;
  const __nv_bfloat16* Al = a_sel ? g_hlo : g_agglo;
  const __nv_bfloat16* Wh = w_sel ? g_whhhi : g_wihhi;
  const __nv_bfloat16* Wl = w_sel ? g_whhlo : g_wihlo;
  float* C = out_sel ? g_gh : g_gi;
  auto f = [&](int it) -> TilePtrs {
    int k0 = it * 32;
    TilePtrs p;
    p.ah = Ah + (size_t)row0 * DD + k0;
    p.al = Al + (size_t)row0 * DD + k0;
    p.bh = Wh + (size_t)col0 * DD + k0;
    p.bl = Wl + (size_t)col0 * DD + k0;
    return p;
  };
  float acc[2][8][4];
  gemm_mma(f, 16, DD, DD, acc);
  const int lane = threadIdx.x & 31, w = threadIdx.x >> 5;
  const int wm = w & 3, wn = w >> 2, grp = lane >> 2, tig = lane & 3;
  #pragma unroll
  for (int mt = 0; mt < 2; ++mt)
    #pragma unroll
    for (int nt = 0; nt < 8; ++nt)
      #pragma unroll
      for (int cr = 0; cr < 4; ++cr) {
        int row = row0 + wm * 32 + mt * 16 + grp + ((cr >> 1) << 3);
        int e = col0 + wn * 64 + nt * 8 + tig * 2 + (cr & 1);
        C[(size_t)row * TD + e] = acc[mt][nt][cr] + bias[e];
      }
}

// ---------------------------------------------------------------------------
// Split & misc kernels
// ---------------------------------------------------------------------------
__global__ void k_split(const float4* __restrict__ s, __nv_bfloat162* __restrict__ hi,
                        __nv_bfloat162* __restrict__ lo, int n4) {
  int i = blockIdx.x * blockDim.x + threadIdx.x;
  if (i >= n4) return;
  float4 v = s[i];
  __nv_bfloat16 hx = __float2bfloat16(v.x), hy = __float2bfloat16(v.y);
  __nv_bfloat16 hz = __float2bfloat16(v.z), hw = __float2bfloat16(v.w);
  __nv_bfloat162 h0; h0.x = hx; h0.y = hy;
  __nv_bfloat162 h1; h1.x = hz; h1.y = hw;
  __nv_bfloat162 l0; l0.x = __float2bfloat16(v.x - __bfloat162float(hx));
                     l0.y = __float2bfloat16(v.y - __bfloat162float(hy));
  __nv_bfloat162 l1; l1.x = __float2bfloat16(v.z - __bfloat162float(hz));
                     l1.y = __float2bfloat16(v.w - __bfloat162float(hw));
  hi[2*i] = h0; hi[2*i+1] = h1;
  lo[2*i] = l0; lo[2*i+1] = l1;
}

__global__ void k_bias(const float* __restrict__ mb) {
  int d = threadIdx.x;
  float s = 0.f;
  #pragma unroll
  for (int r = 0; r < RR; ++r) s += mb[r * DD + d];
  g_bias_sum[d] = s;
}

__global__ void k_gru(const float* __restrict__ nodes, int step) {
  int idx = blockIdx.x * blockDim.x + threadIdx.x;
  const float* hsrc = (step == 0) ? nodes : g_h;
  int d = idx & (DD - 1);
  int row = idx >> 9;
  const float* gi = g_gi + (size_t)row * TD;
  const float* gh = g_gh + (size_t)row * TD;
  float ir = gi[d],        hr = gh[d];
  float iz = gi[DD + d],   hz = gh[DD + d];
  float in_ = gi[2*DD + d], hn = gh[2*DD + d];
  float r = 1.f / (1.f + expf(-(ir + hr)));
  float z = 1.f / (1.f + expf(-(iz + hz)));
  float n = tanhf(in_ + r * hn);
  float h = hsrc[idx];
  float hnew = (1.f - z) * n + z * h;
  g_h[idx] = hnew;
  __nv_bfloat16 hh = __float2bfloat16(hnew);
  g_hhi[idx] = hh;
  g_hlo[idx] = __float2bfloat16(hnew - __bfloat162float(hh));
}

__global__ void k_mean(float* __restrict__ out) {
  int b = blockIdx.x, d = threadIdx.x;
  const float* hp = g_h + (size_t)b * NN * DD + d;
  float s = 0.f;
  for (int i = 0; i < NN; ++i) s += hp[(size_t)i * DD];
  out[b * DD + d] = s * (1.0f / NN);
}

// ---------------------------------------------------------------------------
extern "C" void kernel_launch(void* const* d_in, const int* in_sizes, int n_in,
                              void* d_out, int out_size) {
  const float* nodes = (const float*)d_in[0];
  const float* edges = (const float*)d_in[1];
  const float* msg_W = (const float*)d_in[2];
  const float* msg_b = (const float*)d_in[3];
  const float* b_ih  = (const float*)d_in[6];
  const float* b_hh  = (const float*)d_in[7];
  float* out = (float*)d_out;

  cudaFuncSetAttribute(k_hw_t,    cudaFuncAttributeMaxDynamicSharedMemorySize, DYN_SMEM);
  cudaFuncSetAttribute(k_agg_t,   cudaFuncAttributeMaxDynamicSharedMemorySize, DYN_SMEM);
  cudaFuncSetAttribute(k_gates_t, cudaFuncAttributeMaxDynamicSharedMemorySize, DYN_SMEM);

  __nv_bfloat162 *hhi2, *hlo2, *ehi2, *elo2, *whi2, *wlo2, *ihhi2, *ihlo2, *hhhi2, *hhlo2;
  cudaGetSymbolAddress((void**)&hhi2,  g_hhi);   cudaGetSymbolAddress((void**)&hlo2,  g_hlo);
  cudaGetSymbolAddress((void**)&ehi2,  g_ehi);   cudaGetSymbolAddress((void**)&elo2,  g_elo);
  cudaGetSymbolAddress((void**)&whi2,  g_Whi);   cudaGetSymbolAddress((void**)&wlo2,  g_Wlo);
  cudaGetSymbolAddress((void**)&ihhi2, g_wihhi); cudaGetSymbolAddress((void**)&ihlo2, g_wihlo);
  cudaGetSymbolAddress((void**)&hhhi2, g_whhhi); cudaGetSymbolAddress((void**)&hhlo2, g_whhlo);

  int n4;
  n4 = BB*NN*DD/4;    k_split<<<n4/256, 256>>>((const float4*)nodes, hhi2, hlo2, n4);
  n4 = BB*RR*NN*NN/4; k_split<<<n4/256, 256>>>((const float4*)edges, ehi2, elo2, n4);
  n4 = RR*DD*DD/4;    k_split<<<n4/256, 256>>>((const float4*)msg_W, whi2, wlo2, n4);
  n4 = TD*DD/4;       k_split<<<n4/256, 256>>>((const float4*)d_in[4], ihhi2, ihlo2, n4);
  n4 = TD*DD/4;       k_split<<<n4/256, 256>>>((const float4*)d_in[5], hhhi2, hhlo2, n4);
  k_bias<<<1, DD>>>(msg_b);

  for (int s = 0; s < 2; ++s) {
    k_hw_t   <<<dim3(64, 4, 8),  256, DYN_SMEM>>>();
    k_agg_t  <<<dim3(4, 4, 16),  256, DYN_SMEM>>>();
    k_gates_t<<<dim3(64, 12),    256, DYN_SMEM>>>(0, 0, b_ih, 0);
    k_gates_t<<<dim3(64, 12),    256, DYN_SMEM>>>(1, 1, b_hh, 1);
    k_gru    <<<(BB*NN*DD)/256, 256>>>(nodes, s);
  }
  k_mean<<<BB, DD>>>(out);
}